// round 3
// baseline (speedup 1.0000x reference)
#include <cuda_runtime.h>
#include <cstdint>

#define T_MAX   32768
#define NLM     543
#define FROW    (NLM*3)        // 1629 floats per frame
#define NL      512            // NORMALIZED_LENGTH
#define NCOL    122            // 61 landmarks x 2
#define SCW     128            // padded scratch row width
#define K1_NB   256            // blocks in k1 (T_MAX/128)

// ------------------------- device scratch (static, no allocs) ---------------
__device__ float g_scratch[(size_t)T_MAX * SCW]; // [t][0..41]=hand, [42..121]=lips(raw, may be NaN)
__device__ int   g_keep[T_MAX];
__device__ int   g_idx[T_MAX];                   // compact s -> original frame t
__device__ int   g_blockcnt[K1_NB];
__device__ int   g_blockoff[K1_NB];
__device__ int   g_b[NL + 1];
__device__ float g_lipsum[80];
__device__ int   g_lipcnt[80];
__device__ float g_lipmean[80];
__device__ float g_mean[NL * NCOL];
__device__ int   g_rowflag[NL];
__device__ int   g_rowoff[NL];

__device__ __forceinline__ float nan0(float v) { return (v == v) ? v : 0.0f; }

// ------------------------- K0: zero accumulators ----------------------------
__global__ void kzero() {
    int t = threadIdx.x;
    if (t < 80) { g_lipsum[t] = 0.0f; g_lipcnt[t] = 0; }
}

// ------------------------- K1: per-frame hand/keep/lips ---------------------
// 256 threads = 8 warps, each warp handles 16 consecutive frames.
__global__ void k1(const float* __restrict__ fr, const int* __restrict__ lips) {
    int lane = threadIdx.x & 31;
    int warp = threadIdx.x >> 5;
    int base = blockIdx.x * 128 + warp * 16;

    int li0 = 0, li1 = 0;
    if (lane < 40) li0 = lips[lane];
    if (lane < 8)  li1 = lips[lane + 32];

    float ls0 = 0.f, ls1 = 0.f, ls2 = 0.f, ls3 = 0.f;
    int   lc0 = 0,   lc1 = 0,   lc2 = 0,   lc3 = 0;
    int   wcnt = 0;

    for (int i = 0; i < 16; i++) {
        int t = base + i;
        const float* f = fr + (size_t)t * FROW;
        float* sc = g_scratch + (size_t)t * SCW;

        float h0 = 0.f, h1 = 0.f;
        if (lane < 21) {
            float lx = f[(468 + lane) * 3 + 0];
            float ly = f[(468 + lane) * 3 + 1];
            float rx = f[(522 + lane) * 3 + 0];
            float ry = f[(522 + lane) * 3 + 1];
            h0 = nan0(lx) + nan0(1.0f - rx);
            h1 = nan0(1.0f - ly) + nan0(1.0f - ry);
            sc[2 * lane]     = h0;
            sc[2 * lane + 1] = h1;
        }
        float s = h0 + h1;
        #pragma unroll
        for (int o = 16; o; o >>= 1) s += __shfl_xor_sync(0xffffffffu, s, o);
        int kp = (s != 0.0f) ? 1 : 0;   // same on all lanes
        if (lane == 0) g_keep[t] = kp;
        wcnt += kp;

        if (lane < 40) {
            float x = f[li0 * 3 + 0];
            float y = f[li0 * 3 + 1];
            sc[42 + 2 * lane]     = x;
            sc[42 + 2 * lane + 1] = y;
            if (kp) {
                if (x == x) { ls0 += x; lc0++; }
                if (y == y) { ls1 += y; lc1++; }
            }
        }
        if (lane < 8) {
            float x = f[li1 * 3 + 0];
            float y = f[li1 * 3 + 1];
            sc[42 + 2 * (lane + 32)]     = x;
            sc[42 + 2 * (lane + 32) + 1] = y;
            if (kp) {
                if (x == x) { ls2 += x; lc2++; }
                if (y == y) { ls3 += y; lc3++; }
            }
        }
    }

    // per-block kept-frame count
    __shared__ int swc[8];
    if (lane == 0) swc[warp] = wcnt;
    __syncthreads();
    if (threadIdx.x == 0) {
        int s = 0;
        #pragma unroll
        for (int w = 0; w < 8; w++) s += swc[w];
        g_blockcnt[blockIdx.x] = s;
    }

    // lip nan-mean partials -> global accumulators
    if (lane < 40) {
        atomicAdd(&g_lipsum[2 * lane],     ls0);
        atomicAdd(&g_lipsum[2 * lane + 1], ls1);
        atomicAdd(&g_lipcnt[2 * lane],     lc0);
        atomicAdd(&g_lipcnt[2 * lane + 1], lc1);
    }
    if (lane < 8) {
        int l = lane + 32;
        atomicAdd(&g_lipsum[2 * l],     ls2);
        atomicAdd(&g_lipsum[2 * l + 1], ls3);
        atomicAdd(&g_lipcnt[2 * l],     lc2);
        atomicAdd(&g_lipcnt[2 * l + 1], lc3);
    }
}

// ------------------------- K2: scan blockcnt, boundaries, lip means ---------
__global__ void k2(int nb) {
    __shared__ int sc[256];
    int t = threadIdx.x;
    int v = (t < nb) ? g_blockcnt[t] : 0;
    sc[t] = v;
    __syncthreads();
    for (int o = 1; o < 256; o <<= 1) {
        int a = (t >= o) ? sc[t - o] : 0;
        __syncthreads();
        sc[t] += a;
        __syncthreads();
    }
    if (t < nb) g_blockoff[t] = sc[t] - v;   // exclusive prefix
    int S = sc[255];                          // total kept frames

    // b = np.linspace(0, S-1, 513).astype(int32): y[k] = double(k) * ((S-1)/512.0), trunc
    double step = (double)(S - 1) / 512.0;
    for (int k = t; k < NL + 1; k += 256) {
        int bk = (k == NL) ? (S - 1) : (int)((double)k * step);
        g_b[k] = bk;
    }

    if (t < 80) {
        int   c = g_lipcnt[t];
        float s = g_lipsum[t];
        g_lipmean[t] = (c == 0) ? 0.0f : s / (float)max(c, 1);
    }
}

// ------------------------- K2b: order-preserving compaction -----------------
__global__ void k2b() {   // grid = nb, 128 threads
    int t  = blockIdx.x * 128 + threadIdx.x;
    int kp = g_keep[t];
    int lane = threadIdx.x & 31;
    int warp = threadIdx.x >> 5;
    unsigned bal = __ballot_sync(0xffffffffu, kp);
    int lpref = __popc(bal & ((1u << lane) - 1u));
    __shared__ int wtot[4];
    if (lane == 0) wtot[warp] = __popc(bal);
    __syncthreads();
    int off = g_blockoff[blockIdx.x];
    for (int w = 0; w < warp; w++) off += wtot[w];
    if (kp) g_idx[off + lpref] = t;
}

// ------------------------- K3: segment means + row flags --------------------
__global__ void k3() {    // grid = 512, 128 threads
    int k = blockIdx.x;
    int j = threadIdx.x;
    __shared__ int   sidx[128];
    __shared__ float red[128];

    int s0 = g_b[k];
    int s1 = g_b[k + 1];
    int cnt = s1 - s0;                 // <= 64 for S <= 32768
    for (int s = j; s < cnt; s += 128) sidx[s] = g_idx[s0 + s];
    __syncthreads();

    float m = 0.0f;
    if (j < NCOL) {
        float lm  = (j >= 42) ? g_lipmean[j - 42] : 0.0f;
        float acc = 0.0f;
        for (int i = 0; i < cnt; i++) {
            float v = g_scratch[(size_t)sidx[i] * SCW + j];
            if (j >= 42 && !(v == v)) v = lm;
            acc += v;
        }
        m = (cnt > 0) ? acc / (float)cnt : 0.0f;
        g_mean[k * NCOL + j] = m;
    }
    red[j] = m;
    __syncthreads();
    #pragma unroll
    for (int o = 64; o; o >>= 1) {
        if (j < o) red[j] += red[j + o];
        __syncthreads();
    }
    if (j == 0) g_rowflag[k] = (red[0] != 0.0f) ? 1 : 0;
}

// ------------------------- K4b: scan row flags ------------------------------
__global__ void k4b() {   // 1 block, 512 threads
    __shared__ int sc[NL];
    int t = threadIdx.x;
    int v = g_rowflag[t];
    sc[t] = v;
    __syncthreads();
    for (int o = 1; o < NL; o <<= 1) {
        int a = (t >= o) ? sc[t - o] : 0;
        __syncthreads();
        sc[t] += a;
        __syncthreads();
    }
    g_rowoff[t] = sc[t] - v;
}

// ------------------------- K4c: compact row write ---------------------------
__global__ void k4c(float* __restrict__ out) {  // grid = 512, 128 threads
    int k = blockIdx.x;
    int j = threadIdx.x;
    if (j < NCOL && g_rowflag[k])
        out[(size_t)g_rowoff[k] * NCOL + j] = g_mean[k * NCOL + j];
}

// ------------------------- launch -------------------------------------------
extern "C" void kernel_launch(void* const* d_in, const int* in_sizes, int n_in,
                              void* d_out, int out_size) {
    const float* frames = (const float*)d_in[0];
    const int*   lips   = (const int*)d_in[1];
    int T  = in_sizes[0] / FROW;   // 32768
    int nb = T / 128;              // 256

    kzero<<<1, 128>>>();
    k1<<<nb, 256>>>(frames, lips);
    k2<<<1, 256>>>(nb);
    k2b<<<nb, 128>>>();
    k3<<<NL, 128>>>();
    k4b<<<1, NL>>>();
    k4c<<<NL, 128>>>((float*)d_out);
}

// round 6
// speedup vs baseline: 2.2311x; 2.2311x over previous
#include <cuda_runtime.h>
#include <cstdint>

#define T_MAX   32768
#define NLM     543
#define FROW    (NLM*3)        // 1629 floats per frame
#define NL      512            // NORMALIZED_LENGTH
#define NCOL    122            // 61 landmarks x 2
#define SCW     128            // padded scratch row width (floats)
#define NB1     512            // k1 blocks (64 frames each)
#define FPW     8              // frames per warp in k1

// ------------------------- device scratch (static, no allocs) ---------------
__device__ float g_scratch[(size_t)T_MAX * SCW]; // [t][0..41]=hand, [42..121]=lips(raw, may be NaN)
__device__ __align__(16) unsigned char g_keepbits[4096]; // byte g = frames g*8..g*8+7
__device__ int   g_chunkoff[256];                // exclusive kept-count per 128-frame chunk
__device__ int   g_idx[T_MAX];                   // compact s -> original frame t
__device__ int   g_b[NL + 1];
__device__ float g_lipsum[80];
__device__ int   g_lipcnt[80];
__device__ float g_lipmean[80];
__device__ int   g_rowoff[NL];

__device__ __forceinline__ float nan0(float v) { return (v == v) ? v : 0.0f; }

// ------------------------- K1: per-frame hand/keep/lips ---------------------
// 512 blocks x 256 threads; 8 warps/block, 8 consecutive frames per warp.
__global__ void k1(const float* __restrict__ fr, const int* __restrict__ lips) {
    __shared__ float ssum[80];
    __shared__ int   scnt[80];
    int tid  = threadIdx.x;
    int lane = tid & 31;
    int warp = tid >> 5;
    if (tid < 80) { ssum[tid] = 0.0f; scnt[tid] = 0; }
    __syncthreads();

    int base = blockIdx.x * 64 + warp * FPW;

    int li0 = 0, li1 = 0;
    if (lane < 40) li0 = lips[lane];
    if (lane < 8)  li1 = lips[lane + 32];

    float ls0 = 0.f, ls1 = 0.f, ls2 = 0.f, ls3 = 0.f;
    int   lc0 = 0,   lc1 = 0,   lc2 = 0,   lc3 = 0;
    unsigned kbits = 0;

    #pragma unroll
    for (int i = 0; i < FPW; i++) {
        int t = base + i;
        const float* f = fr + (size_t)t * FROW;
        float2* sc = (float2*)(g_scratch + (size_t)t * SCW);

        float h0 = 0.f, h1 = 0.f;
        if (lane < 21) {
            float lx = f[1404 + 3 * lane];   // (468+l)*3
            float ly = f[1405 + 3 * lane];
            float rx = f[1566 + 3 * lane];   // (522+l)*3
            float ry = f[1567 + 3 * lane];
            h0 = nan0(lx) + nan0(1.0f - rx);
            h1 = nan0(1.0f - ly) + nan0(1.0f - ry);
            sc[lane] = make_float2(h0, h1);
        }
        // all hand components are >= 0, so sum != 0  <=>  any component != 0
        unsigned anyb = __ballot_sync(0xffffffffu, (h0 + h1) != 0.0f);
        int kp = anyb ? 1 : 0;
        kbits |= (unsigned)kp << i;

        float x0 = 0.f, y0 = 0.f, x1 = 0.f, y1 = 0.f;
        if (lane < 40) {
            x0 = f[3 * li0];
            y0 = f[3 * li0 + 1];
            sc[21 + lane] = make_float2(x0, y0);
        }
        if (lane < 8) {
            x1 = f[3 * li1];
            y1 = f[3 * li1 + 1];
            sc[53 + lane] = make_float2(x1, y1);
        }
        if (kp) {
            if (lane < 40) {
                if (x0 == x0) { ls0 += x0; lc0++; }
                if (y0 == y0) { ls1 += y0; lc1++; }
            }
            if (lane < 8) {
                if (x1 == x1) { ls2 += x1; lc2++; }
                if (y1 == y1) { ls3 += y1; lc3++; }
            }
        }
    }

    if (lane == 0) g_keepbits[blockIdx.x * 8 + warp] = (unsigned char)kbits;

    if (lane < 40) {
        atomicAdd(&ssum[2 * lane],     ls0);
        atomicAdd(&ssum[2 * lane + 1], ls1);
        atomicAdd(&scnt[2 * lane],     lc0);
        atomicAdd(&scnt[2 * lane + 1], lc1);
    }
    if (lane < 8) {
        int c = 64 + 2 * lane;
        atomicAdd(&ssum[c],     ls2);
        atomicAdd(&ssum[c + 1], ls3);
        atomicAdd(&scnt[c],     lc2);
        atomicAdd(&scnt[c + 1], lc3);
    }
    __syncthreads();
    if (tid < 80) {
        atomicAdd(&g_lipsum[tid], ssum[tid]);
        atomicAdd(&g_lipcnt[tid], scnt[tid]);
    }
}

// -------- K2: count scan, boundaries, row offsets, lip means (1 block) ------
__global__ void k2() {
    __shared__ int sc[256];
    __shared__ int sr[NL];
    int t = threadIdx.x;

    // thread t owns frames t*128 .. t*128+127 via 16 keepbit bytes (uint4)
    uint4 kb = ((const uint4*)g_keepbits)[t];
    int cnt = __popc(kb.x) + __popc(kb.y) + __popc(kb.z) + __popc(kb.w);
    sc[t] = cnt;
    __syncthreads();
    for (int o = 1; o < 256; o <<= 1) {
        int a = (t >= o) ? sc[t - o] : 0;
        __syncthreads();
        sc[t] += a;
        __syncthreads();
    }
    g_chunkoff[t] = sc[t] - cnt;   // exclusive prefix
    int S = sc[255];

    // b = np.linspace(0, S-1, 513).astype(int32)
    double step = (double)(S - 1) / 512.0;
    for (int k = t; k < NL + 1; k += 256)
        g_b[k] = (k == NL) ? (S - 1) : (int)((double)k * step);
    __syncthreads();

    // row kept  <=>  segment count > 0 (all values nonnegative, kept frames
    // have strictly positive hand sum => row sum > 0). Exclusive scan of flags.
    int f0 = (g_b[t + 1]   > g_b[t])       ? 1 : 0;
    int f1 = (g_b[t + 257] > g_b[t + 256]) ? 1 : 0;
    sr[t] = f0; sr[t + 256] = f1;
    __syncthreads();
    for (int o = 1; o < NL; o <<= 1) {
        int v0 = sr[t]       + ((t       >= o) ? sr[t - o]       : 0);
        int v1 = sr[t + 256] + ((t + 256 >= o) ? sr[t + 256 - o] : 0);
        __syncthreads();
        sr[t] = v0; sr[t + 256] = v1;
        __syncthreads();
    }
    g_rowoff[t]       = sr[t]       - f0;
    g_rowoff[t + 256] = sr[t + 256] - f1;

    if (t < 80) {
        int   c = g_lipcnt[t];
        float s = g_lipsum[t];
        g_lipmean[t] = (c == 0) ? 0.0f : s / (float)max(c, 1);
    }
}

// ---------- K2b: order-preserving compaction from bitmask -------------------
__global__ void k2b() {   // grid = 256, 128 threads (one 128-frame chunk each)
    __shared__ unsigned w[4];
    int j = threadIdx.x;
    int b = blockIdx.x;
    if (j < 4) w[j] = ((const unsigned*)g_keepbits)[b * 4 + j];
    __syncthreads();
    unsigned w0 = w[0], w1 = w[1], w2 = w[2], w3 = w[3];
    int word = j >> 5, bit = j & 31;
    unsigned mw = (word == 0) ? w0 : (word == 1) ? w1 : (word == 2) ? w2 : w3;
    int kp  = (mw >> bit) & 1;
    int pre = __popc(mw & ((1u << bit) - 1u));
    if (word > 0) pre += __popc(w0);
    if (word > 1) pre += __popc(w1);
    if (word > 2) pre += __popc(w2);
    if (kp) g_idx[g_chunkoff[b] + pre] = b * 128 + j;
}

// ---------- K3: segment means -> compacted output rows ----------------------
__global__ void k3(float* __restrict__ out) {  // grid = 512, 128 threads
    int k = blockIdx.x;
    int j = threadIdx.x;

    // reset accumulators for next graph replay (k2 already consumed them)
    if (k == 0 && j < 80) { g_lipsum[j] = 0.0f; g_lipcnt[j] = 0; }

    __shared__ int sidx[80];
    int s0 = g_b[k];
    int s1 = g_b[k + 1];
    int cnt = s1 - s0;                 // <= 64 for S <= 32768
    if (cnt <= 0) return;

    for (int s = j; s < cnt; s += 128) sidx[s] = g_idx[s0 + s];
    __syncthreads();
    if (j >= NCOL) return;

    float lm = (j >= 42) ? g_lipmean[j - 42] : 0.0f;  // hand cols never NaN
    float a0 = 0.f, a1 = 0.f, a2 = 0.f, a3 = 0.f;
    int i = 0;
    for (; i + 4 <= cnt; i += 4) {
        float v0 = g_scratch[(size_t)sidx[i]     * SCW + j];
        float v1 = g_scratch[(size_t)sidx[i + 1] * SCW + j];
        float v2 = g_scratch[(size_t)sidx[i + 2] * SCW + j];
        float v3 = g_scratch[(size_t)sidx[i + 3] * SCW + j];
        a0 += (v0 == v0) ? v0 : lm;
        a1 += (v1 == v1) ? v1 : lm;
        a2 += (v2 == v2) ? v2 : lm;
        a3 += (v3 == v3) ? v3 : lm;
    }
    for (; i < cnt; i++) {
        float v = g_scratch[(size_t)sidx[i] * SCW + j];
        a0 += (v == v) ? v : lm;
    }
    float mean = ((a0 + a1) + (a2 + a3)) / (float)cnt;
    out[(size_t)g_rowoff[k] * NCOL + j] = mean;
}

// ------------------------- launch -------------------------------------------
extern "C" void kernel_launch(void* const* d_in, const int* in_sizes, int n_in,
                              void* d_out, int out_size) {
    const float* frames = (const float*)d_in[0];
    const int*   lips   = (const int*)d_in[1];

    k1<<<NB1, 256>>>(frames, lips);
    k2<<<1, 256>>>();
    k2b<<<256, 128>>>();
    k3<<<NL, 128>>>((float*)d_out);
}